// round 2
// baseline (speedup 1.0000x reference)
#include <cuda_runtime.h>

#define NN_MAX 100000
#define EE_MAX 1600000
#define ETOT_MAX (EE_MAX + NN_MAX)
#define NEGSLOPE 0.2f
#define EPSV 1e-16f

// ---------------- scratch (static device allocations) ----------------
__device__ int                 g_cnt[NN_MAX];
__device__ int                 g_rowptr[NN_MAX + 1];
__device__ int                 g_cur[NN_MAX];
__device__ int                 g_src[ETOT_MAX];
__device__ int                 g_dst[ETOT_MAX];
__device__ int                 g_perm[ETOT_MAX];   // CSR pos -> original edge id
__device__ int                 g_csrc[ETOT_MAX];   // CSR pos -> src node
__device__ __align__(16) float g_xl[NN_MAX * 64];
__device__ __align__(16) float g_xr[NN_MAX * 64];
__device__ __align__(16) float g_h [NN_MAX * 64];
__device__ float4              g_sc[ETOT_MAX];     // per CSR pos: 4 head scores -> exp values

// ---------------- CSR build ----------------
__global__ void k_zero(int n) {
    int i = blockIdx.x * blockDim.x + threadIdx.x;
    if (i < n) g_cnt[i] = 0;
}

__global__ void k_convert(const int* __restrict__ ei, int E, int etot) {
    int e = blockIdx.x * blockDim.x + threadIdx.x;
    if (e >= etot) return;
    int s, d;
    if (e < E) { s = ei[e]; d = ei[E + e]; }
    else       { s = d = e - E; }                     // self loops appended
    g_src[e] = s;
    g_dst[e] = d;
    atomicAdd(&g_cnt[d], 1);
}

// single-block exclusive scan over g_cnt -> g_rowptr / g_cur
__global__ void k_scan(int n) {
    __shared__ int wsum[32];
    __shared__ int carrysh;
    int tid = threadIdx.x, lane = tid & 31, wid = tid >> 5;
    if (tid == 0) carrysh = 0;
    __syncthreads();
    for (int base = 0; base < n; base += 1024) {
        int idx = base + tid;
        int v = (idx < n) ? g_cnt[idx] : 0;
        int incl = v;
        #pragma unroll
        for (int off = 1; off < 32; off <<= 1) {
            int t = __shfl_up_sync(0xffffffffu, incl, off);
            if (lane >= off) incl += t;
        }
        if (lane == 31) wsum[wid] = incl;
        __syncthreads();
        if (wid == 0) {
            int s = wsum[lane];
            #pragma unroll
            for (int off = 1; off < 32; off <<= 1) {
                int t = __shfl_up_sync(0xffffffffu, s, off);
                if (lane >= off) s += t;
            }
            wsum[lane] = s;
        }
        __syncthreads();
        int woff = (wid == 0) ? 0 : wsum[wid - 1];
        int excl = carrysh + woff + incl - v;
        if (idx < n) { g_rowptr[idx] = excl; g_cur[idx] = excl; }
        __syncthreads();
        if (tid == 0) carrysh += wsum[31];
        __syncthreads();
    }
    if (threadIdx.x == 0) g_rowptr[n] = carrysh;
}

__global__ void k_scatter(int etot) {
    int e = blockIdx.x * blockDim.x + threadIdx.x;
    if (e >= etot) return;
    int d = g_dst[e];
    int pos = atomicAdd(&g_cur[d], 1);
    g_perm[pos] = e;
    g_csrc[pos] = g_src[e];
}

// ---------------- GEMM: out[n][64] = x[n][K] @ W[K][64] + b ----------------
// block = 256 threads = 8 warps, each warp handles 4 rows per batch.
template <int K>
__global__ void k_gemm(const float* __restrict__ xext, int x_from_gh,
                       const float* __restrict__ W, const float* __restrict__ b,
                       int out_sel /*0: g_xl, 1: g_xr*/, int nrows) {
    __shared__ float sW[K * 64];
    __shared__ float sX[8][4 * K];
    const float* x = x_from_gh ? g_h : xext;
    float* out = out_sel ? g_xr : g_xl;

    for (int i = threadIdx.x; i < K * 64; i += 256) sW[i] = W[i];
    __syncthreads();

    int warp = threadIdx.x >> 5, lane = threadIdx.x & 31;
    float2 bv = ((const float2*)b)[lane];

    for (int base = (blockIdx.x * 8 + warp) * 4; base < nrows; base += gridDim.x * 32) {
        float* sx = sX[warp];
        #pragma unroll
        for (int r = 0; r < 4; r++) {
            int row = base + r;
            if (row < nrows) {
                #pragma unroll
                for (int k = lane; k < K; k += 32) sx[r * K + k] = x[(size_t)row * K + k];
            }
        }
        __syncwarp();
        float2 acc[4] = {{0.f,0.f},{0.f,0.f},{0.f,0.f},{0.f,0.f}};
        #pragma unroll 8
        for (int k = 0; k < K; k++) {
            float2 w = *(const float2*)&sW[k * 64 + 2 * lane];
            #pragma unroll
            for (int r = 0; r < 4; r++) {
                float xv = sx[r * K + k];
                acc[r].x += xv * w.x;
                acc[r].y += xv * w.y;
            }
        }
        #pragma unroll
        for (int r = 0; r < 4; r++) {
            int row = base + r;
            if (row < nrows) {
                float2 o = make_float2(acc[r].x + bv.x, acc[r].y + bv.y);
                *(float2*)&out[(size_t)row * 64 + 2 * lane] = o;
            }
        }
        __syncwarp();
    }
}

// ---------------- per-node GATv2 edge phase (one warp per dst node) -------
// lane covers feature indices {2*lane, 2*lane+1}; head = lane>>3.
__global__ void k_node(int out_to_gh, float* __restrict__ outext,
                       const float* __restrict__ att, const float* __restrict__ bias,
                       float* __restrict__ alpha, int n) {
    int node = blockIdx.x * 8 + (threadIdx.x >> 5);
    if (node >= n) return;
    int lane = threadIdx.x & 31;
    int head = lane >> 3;
    float* outp = out_to_gh ? g_h : outext;

    int rs = g_rowptr[node], re = g_rowptr[node + 1];
    float2 xrv = *(const float2*)&g_xr[(size_t)node * 64 + 2 * lane];
    float2 av  = ((const float2*)att)[lane];

    // pass 1: scores + per-head running max
    float cmax = -1e30f;
    for (int pos = rs; pos < re; pos++) {
        int s = g_csrc[pos];
        float2 xlv = *(const float2*)&g_xl[(size_t)s * 64 + 2 * lane];
        float mx = xlv.x + xrv.x;
        float my = xlv.y + xrv.y;
        mx = mx > 0.f ? mx : NEGSLOPE * mx;
        my = my > 0.f ? my : NEGSLOPE * my;
        float p = mx * av.x + my * av.y;
        p += __shfl_xor_sync(0xffffffffu, p, 1);
        p += __shfl_xor_sync(0xffffffffu, p, 2);
        p += __shfl_xor_sync(0xffffffffu, p, 4);   // full head sum in all 8 lanes
        if ((lane & 7) == 0) ((float*)&g_sc[pos])[head] = p;
        cmax = fmaxf(cmax, p);
    }
    __syncwarp();
    float hm0 = __shfl_sync(0xffffffffu, cmax, 0);
    float hm1 = __shfl_sync(0xffffffffu, cmax, 8);
    float hm2 = __shfl_sync(0xffffffffu, cmax, 16);
    float hm3 = __shfl_sync(0xffffffffu, cmax, 24);

    // pass 2: exp + denom (lane-parallel over positions)
    float d0 = 0.f, d1 = 0.f, d2 = 0.f, d3 = 0.f;
    for (int pos = rs + lane; pos < re; pos += 32) {
        float4 s = g_sc[pos];
        float e0 = __expf(s.x - hm0);
        float e1 = __expf(s.y - hm1);
        float e2 = __expf(s.z - hm2);
        float e3 = __expf(s.w - hm3);
        g_sc[pos] = make_float4(e0, e1, e2, e3);
        d0 += e0; d1 += e1; d2 += e2; d3 += e3;
    }
    #pragma unroll
    for (int off = 16; off; off >>= 1) {
        d0 += __shfl_xor_sync(0xffffffffu, d0, off);
        d1 += __shfl_xor_sync(0xffffffffu, d1, off);
        d2 += __shfl_xor_sync(0xffffffffu, d2, off);
        d3 += __shfl_xor_sync(0xffffffffu, d3, off);
    }
    float dh  = (head == 0) ? d0 : (head == 1) ? d1 : (head == 2) ? d2 : d3;
    float rcp = 1.f / (dh + EPSV);
    __syncwarp();

    // pass 3: alpha output + weighted aggregation
    float2 acc = make_float2(0.f, 0.f);
    for (int pos = rs; pos < re; pos++) {
        int s = g_csrc[pos];
        float e = ((const float*)&g_sc[pos])[head];   // broadcast within head group
        float a = e * rcp;
        float2 xlv = *(const float2*)&g_xl[(size_t)s * 64 + 2 * lane];
        acc.x += a * xlv.x;
        acc.y += a * xlv.y;
        if ((lane & 7) == 0) alpha[(size_t)g_perm[pos] * 4 + head] = a;
    }
    float2 bv = ((const float2*)bias)[lane];
    float ox = fmaxf(acc.x + bv.x, 0.f);
    float oy = fmaxf(acc.y + bv.y, 0.f);
    *(float2*)&outp[(size_t)node * 64 + 2 * lane] = make_float2(ox, oy);
}

// ---------------- launch ----------------
extern "C" void kernel_launch(void* const* d_in, const int* in_sizes, int n_in,
                              void* d_out, int out_size) {
    const float* x     = (const float*)d_in[0];
    const int*   ei    = (const int*)d_in[1];      // JAX x64 disabled -> int32
    const float* Wl1   = (const float*)d_in[2];
    const float* bl1   = (const float*)d_in[3];
    const float* Wr1   = (const float*)d_in[4];
    const float* br1   = (const float*)d_in[5];
    const float* att1  = (const float*)d_in[6];
    const float* bias1 = (const float*)d_in[7];
    const float* Wl2   = (const float*)d_in[8];
    const float* bl2   = (const float*)d_in[9];
    const float* Wr2   = (const float*)d_in[10];
    const float* br2   = (const float*)d_in[11];
    const float* att2  = (const float*)d_in[12];
    const float* bias2 = (const float*)d_in[13];

    int n    = in_sizes[0] / 128;  // 100000
    int E    = in_sizes[1] / 2;    // 1600000
    int etot = E + n;              // 1700000

    float* out    = (float*)d_out;
    float* outh   = out;
    float* alpha1 = out + (size_t)n * 64;
    float* alpha2 = alpha1 + (size_t)etot * 4;

    // CSR build (shared by both layers)
    k_zero<<<(n + 255) / 256, 256>>>(n);
    k_convert<<<(etot + 255) / 256, 256>>>(ei, E, etot);
    k_scan<<<1, 1024>>>(n);
    k_scatter<<<(etot + 255) / 256, 256>>>(etot);

    int gemm_grid = (n + 31) / 32;

    // layer 1
    k_gemm<128><<<gemm_grid, 256>>>(x, 0, Wl1, bl1, /*out=g_xl*/0, n);
    k_gemm<128><<<gemm_grid, 256>>>(x, 0, Wr1, br1, /*out=g_xr*/1, n);
    k_node<<<(n + 7) / 8, 256>>>(/*out_to_gh=*/1, nullptr, att1, bias1, alpha1, n);

    // layer 2 (input = g_h)
    k_gemm<64><<<gemm_grid, 256>>>(nullptr, 1, Wl2, bl2, 0, n);
    k_gemm<64><<<gemm_grid, 256>>>(nullptr, 1, Wr2, br2, 1, n);
    k_node<<<(n + 7) / 8, 256>>>(/*out_to_gh=*/0, outh, att2, bias2, alpha2, n);
}

// round 3
// speedup vs baseline: 1.4729x; 1.4729x over previous
#include <cuda_runtime.h>

#define NN_MAX 100000
#define EE_MAX 1600000
#define ETOT_MAX (EE_MAX + NN_MAX)
#define NEGSLOPE 0.2f
#define EPSV 1e-16f
#define SCHUNK 512

// ---------------- scratch (static device allocations) ----------------
__device__ int                 g_cnt[NN_MAX];
__device__ int                 g_rowptr[NN_MAX + 1];
__device__ int                 g_cur[NN_MAX];
__device__ int                 g_src[ETOT_MAX];
__device__ int                 g_dst[ETOT_MAX];
__device__ int                 g_perm[ETOT_MAX];   // CSR pos -> original edge id
__device__ int                 g_csrc[ETOT_MAX];   // CSR pos -> src node
__device__ int                 g_bsum[(NN_MAX + SCHUNK - 1) / SCHUNK + 1];
__device__ __align__(16) float g_xl[NN_MAX * 64];
__device__ __align__(16) float g_xr[NN_MAX * 64];
__device__ __align__(16) float g_h [NN_MAX * 64];
__device__ float4              g_sc[ETOT_MAX];     // per CSR pos: exp(score) per head

// ---------------- CSR build ----------------
__global__ void k_zero(int n) {
    int i = blockIdx.x * blockDim.x + threadIdx.x;
    if (i < n) g_cnt[i] = 0;
}

__global__ void k_convert(const int* __restrict__ ei, int E, int etot) {
    int e = blockIdx.x * blockDim.x + threadIdx.x;
    if (e >= etot) return;
    int s, d;
    if (e < E) { s = ei[e]; d = ei[E + e]; }
    else       { s = d = e - E; }                     // self loops appended
    g_src[e] = s;
    g_dst[e] = d;
    atomicAdd(&g_cnt[d], 1);
}

// --- 3-stage multi-block exclusive scan of g_cnt -> g_rowptr / g_cur -----
__global__ void k_scanA(int n) {          // block sums, SCHUNK elems / block, 512 thr
    int idx = blockIdx.x * SCHUNK + threadIdx.x;
    int v = (idx < n) ? g_cnt[idx] : 0;
    __shared__ int wsum[16];
    int lane = threadIdx.x & 31, wid = threadIdx.x >> 5;
    int s = v;
    #pragma unroll
    for (int off = 1; off < 32; off <<= 1) {
        int t = __shfl_up_sync(0xffffffffu, s, off);
        if (lane >= off) s += t;
    }
    if (lane == 31) wsum[wid] = s;
    __syncthreads();
    if (threadIdx.x == 0) {
        int tot = 0;
        #pragma unroll
        for (int w = 0; w < 16; w++) tot += wsum[w];
        g_bsum[blockIdx.x] = tot;
    }
}

__global__ void k_scanB(int nb, int n) {  // 1 block, 256 thr, scans <=256 block sums
    __shared__ int wsum[8];
    int lane = threadIdx.x & 31, wid = threadIdx.x >> 5;
    int v = (threadIdx.x < nb) ? g_bsum[threadIdx.x] : 0;
    int incl = v;
    #pragma unroll
    for (int off = 1; off < 32; off <<= 1) {
        int t = __shfl_up_sync(0xffffffffu, incl, off);
        if (lane >= off) incl += t;
    }
    if (lane == 31) wsum[wid] = incl;
    __syncthreads();
    if (wid == 0 && lane < 8) {
        int s = wsum[lane];
        #pragma unroll
        for (int off = 1; off < 8; off <<= 1) {
            int t = __shfl_up_sync(0xffu, s, off);
            if (lane >= off) s += t;
        }
        wsum[lane] = s;
    }
    __syncthreads();
    int woff = (wid == 0) ? 0 : wsum[wid - 1];
    int excl = woff + incl - v;
    if (threadIdx.x < nb) g_bsum[threadIdx.x] = excl;
    if (threadIdx.x == nb - 1) g_rowptr[n] = excl + v;
}

__global__ void k_scanC(int n) {          // in-chunk exclusive scan + block offset
    int idx = blockIdx.x * SCHUNK + threadIdx.x;
    int v = (idx < n) ? g_cnt[idx] : 0;
    __shared__ int wsum[16];
    int lane = threadIdx.x & 31, wid = threadIdx.x >> 5;
    int incl = v;
    #pragma unroll
    for (int off = 1; off < 32; off <<= 1) {
        int t = __shfl_up_sync(0xffffffffu, incl, off);
        if (lane >= off) incl += t;
    }
    if (lane == 31) wsum[wid] = incl;
    __syncthreads();
    if (wid == 0 && lane < 16) {
        int s = wsum[lane];
        #pragma unroll
        for (int off = 1; off < 16; off <<= 1) {
            int t = __shfl_up_sync(0xffffu, s, off);
            if (lane >= off) s += t;
        }
        wsum[lane] = s;
    }
    __syncthreads();
    int woff = (wid == 0) ? 0 : wsum[wid - 1];
    int excl = g_bsum[blockIdx.x] + woff + incl - v;
    if (idx < n) { g_rowptr[idx] = excl; g_cur[idx] = excl; }
}

__global__ void k_scatter(int etot) {
    int e = blockIdx.x * blockDim.x + threadIdx.x;
    if (e >= etot) return;
    int d = g_dst[e];
    int pos = atomicAdd(&g_cur[d], 1);
    g_perm[pos] = e;
    g_csrc[pos] = g_src[e];
}

// ---- dual GEMM: g_xl = x@Wl + bl, g_xr = x@Wr + br  (64 output cols) ----
// 256 threads = 8 warps; warp handles 4 rows; lane handles 2 cols of each W.
template <int K>
__global__ void k_gemm2(const float* __restrict__ xext, int from_gh,
                        const float* __restrict__ Wl, const float* __restrict__ bl,
                        const float* __restrict__ Wr, const float* __restrict__ br,
                        int nrows) {
    extern __shared__ float sm[];
    float* sWl = sm;                 // K*64
    float* sWr = sm + K * 64;        // K*64
    float* sX  = sm + 2 * K * 64;    // 8 * 4 * K
    const float* x = from_gh ? g_h : xext;

    for (int i = threadIdx.x; i < K * 64; i += 256) { sWl[i] = Wl[i]; sWr[i] = Wr[i]; }
    __syncthreads();

    int warp = threadIdx.x >> 5, lane = threadIdx.x & 31;
    float2 bvl = ((const float2*)bl)[lane];
    float2 bvr = ((const float2*)br)[lane];
    float* sx = sX + warp * 4 * K;

    for (int base = (blockIdx.x * 8 + warp) * 4; base < nrows; base += gridDim.x * 32) {
        #pragma unroll
        for (int r = 0; r < 4; r++) {
            int row = base + r;
            if (row < nrows) {
                #pragma unroll
                for (int k = lane; k < K; k += 32) sx[r * K + k] = x[(size_t)row * K + k];
            }
        }
        __syncwarp();
        float2 accl[4] = {{0.f,0.f},{0.f,0.f},{0.f,0.f},{0.f,0.f}};
        float2 accr[4] = {{0.f,0.f},{0.f,0.f},{0.f,0.f},{0.f,0.f}};
        #pragma unroll 2
        for (int k0 = 0; k0 < K; k0 += 4) {
            float4 xv[4];
            #pragma unroll
            for (int r = 0; r < 4; r++) xv[r] = *(const float4*)&sx[r * K + k0];
            #pragma unroll
            for (int kk = 0; kk < 4; kk++) {
                float2 wl = *(const float2*)&sWl[(k0 + kk) * 64 + 2 * lane];
                float2 wr = *(const float2*)&sWr[(k0 + kk) * 64 + 2 * lane];
                #pragma unroll
                for (int r = 0; r < 4; r++) {
                    float xs = ((const float*)&xv[r])[kk];
                    accl[r].x = fmaf(xs, wl.x, accl[r].x);
                    accl[r].y = fmaf(xs, wl.y, accl[r].y);
                    accr[r].x = fmaf(xs, wr.x, accr[r].x);
                    accr[r].y = fmaf(xs, wr.y, accr[r].y);
                }
            }
        }
        #pragma unroll
        for (int r = 0; r < 4; r++) {
            int row = base + r;
            if (row < nrows) {
                *(float2*)&g_xl[(size_t)row * 64 + 2 * lane] =
                    make_float2(accl[r].x + bvl.x, accl[r].y + bvl.y);
                *(float2*)&g_xr[(size_t)row * 64 + 2 * lane] =
                    make_float2(accr[r].x + bvr.x, accr[r].y + bvr.y);
            }
        }
        __syncwarp();
    }
}

// ---- fused per-node edge phase: one gather pass (no max-shift; scores O(1)),
//      then lane-parallel alpha writeback. One warp per dst node. ----------
__global__ void k_node(int out_to_gh, float* __restrict__ outext,
                       const float* __restrict__ att, const float* __restrict__ bias,
                       float* __restrict__ alpha, int n) {
    int node = blockIdx.x * 8 + (threadIdx.x >> 5);
    if (node >= n) return;
    int lane = threadIdx.x & 31;
    int head = lane >> 3;
    float* outp = out_to_gh ? g_h : outext;

    int rs = g_rowptr[node], re = g_rowptr[node + 1];
    float2 xrv = *(const float2*)&g_xr[(size_t)node * 64 + 2 * lane];
    float2 av  = ((const float2*)att)[lane];

    float denom = 0.f;
    float2 acc = make_float2(0.f, 0.f);
    for (int pos = rs; pos < re; pos++) {
        int s = g_csrc[pos];
        float2 xlv = *(const float2*)&g_xl[(size_t)s * 64 + 2 * lane];
        float mx = xlv.x + xrv.x;
        float my = xlv.y + xrv.y;
        mx = mx > 0.f ? mx : NEGSLOPE * mx;
        my = my > 0.f ? my : NEGSLOPE * my;
        float p = mx * av.x + my * av.y;
        p += __shfl_xor_sync(0xffffffffu, p, 1);
        p += __shfl_xor_sync(0xffffffffu, p, 2);
        p += __shfl_xor_sync(0xffffffffu, p, 4);   // head-group sum in all 8 lanes
        float e = __expf(p);
        if ((lane & 7) == 0) ((float*)&g_sc[pos])[head] = e;
        denom += e;
        acc.x = fmaf(e, xlv.x, acc.x);
        acc.y = fmaf(e, xlv.y, acc.y);
    }
    float rcp = 1.f / (denom + EPSV);

    float2 bv = ((const float2*)bias)[lane];
    float ox = fmaxf(fmaf(acc.x, rcp, bv.x), 0.f);
    float oy = fmaxf(fmaf(acc.y, rcp, bv.y), 0.f);
    *(float2*)&outp[(size_t)node * 64 + 2 * lane] = make_float2(ox, oy);

    // alpha writeback: lane-parallel over CSR positions, float4 per edge
    float r0 = __shfl_sync(0xffffffffu, rcp, 0);
    float r1 = __shfl_sync(0xffffffffu, rcp, 8);
    float r2 = __shfl_sync(0xffffffffu, rcp, 16);
    float r3 = __shfl_sync(0xffffffffu, rcp, 24);
    __syncwarp();
    for (int pos = rs + lane; pos < re; pos += 32) {
        float4 e4 = g_sc[pos];
        float4 a4 = make_float4(e4.x * r0, e4.y * r1, e4.z * r2, e4.w * r3);
        *(float4*)&alpha[(size_t)g_perm[pos] * 4] = a4;
    }
}

// ---------------- launch ----------------
extern "C" void kernel_launch(void* const* d_in, const int* in_sizes, int n_in,
                              void* d_out, int out_size) {
    const float* x     = (const float*)d_in[0];
    const int*   ei    = (const int*)d_in[1];      // int32 edge index
    const float* Wl1   = (const float*)d_in[2];
    const float* bl1   = (const float*)d_in[3];
    const float* Wr1   = (const float*)d_in[4];
    const float* br1   = (const float*)d_in[5];
    const float* att1  = (const float*)d_in[6];
    const float* bias1 = (const float*)d_in[7];
    const float* Wl2   = (const float*)d_in[8];
    const float* bl2   = (const float*)d_in[9];
    const float* Wr2   = (const float*)d_in[10];
    const float* br2   = (const float*)d_in[11];
    const float* att2  = (const float*)d_in[12];
    const float* bias2 = (const float*)d_in[13];

    int n    = in_sizes[0] / 128;  // 100000
    int E    = in_sizes[1] / 2;    // 1600000
    int etot = E + n;              // 1700000
    int nb   = (n + SCHUNK - 1) / SCHUNK;

    float* out    = (float*)d_out;
    float* outh   = out;
    float* alpha1 = out + (size_t)n * 64;
    float* alpha2 = alpha1 + (size_t)etot * 4;

    // dynamic smem opt-in for the K=128 dual GEMM (81920 B)
    static int smem_set = 0;
    (void)smem_set;
    cudaFuncSetAttribute(k_gemm2<128>, cudaFuncAttributeMaxDynamicSharedMemorySize, 81920);

    // CSR build (shared by both layers)
    k_zero<<<(n + 255) / 256, 256>>>(n);
    k_convert<<<(etot + 255) / 256, 256>>>(ei, E, etot);
    k_scanA<<<nb, SCHUNK>>>(n);
    k_scanB<<<1, 256>>>(nb, n);
    k_scanC<<<nb, SCHUNK>>>(n);
    k_scatter<<<(etot + 255) / 256, 256>>>(etot);

    // layer 1
    k_gemm2<128><<<592, 256, 81920>>>(x, 0, Wl1, bl1, Wr1, br1, n);
    k_node<<<(n + 7) / 8, 256>>>(/*out_to_gh=*/1, nullptr, att1, bias1, alpha1, n);

    // layer 2 (input = g_h)
    k_gemm2<64><<<592, 256, 40960>>>(nullptr, 1, Wl2, bl2, Wr2, br2, n);
    k_node<<<(n + 7) / 8, 256>>>(/*out_to_gh=*/0, outh, att2, bias2, alpha2, n);
}

// round 4
// speedup vs baseline: 1.7704x; 1.2020x over previous
#include <cuda_runtime.h>

#define NN_MAX 100000
#define EE_MAX 1600000
#define ETOT_MAX (EE_MAX + NN_MAX)
#define NEGSLOPE 0.2f
#define EPSV 1e-16f
#define SCHUNK 512

// ---------------- scratch (static device allocations) ----------------
__device__ int                 g_cnt[NN_MAX];
__device__ int                 g_rowptr[NN_MAX + 1];
__device__ int                 g_cur[NN_MAX];
__device__ int                 g_perm[ETOT_MAX];   // CSR pos -> original edge id
__device__ int                 g_csrc[ETOT_MAX];   // CSR pos -> src node
__device__ int                 g_bsum[(NN_MAX + SCHUNK - 1) / SCHUNK + 1];
__device__ __align__(16) float g_xl[NN_MAX * 64];
__device__ __align__(16) float g_xr[NN_MAX * 64];
__device__ __align__(16) float g_h [NN_MAX * 64];
__device__ float4              g_sc[ETOT_MAX];     // per CSR pos: exp(score) per head

// ---------------- CSR build ----------------
__global__ void k_zero(int n) {
    int i = blockIdx.x * blockDim.x + threadIdx.x;
    if (i < n) g_cnt[i] = 0;
}

__global__ void k_count(const int* __restrict__ ei, int E, int etot) {
    int e = blockIdx.x * blockDim.x + threadIdx.x;
    if (e >= etot) return;
    int d = (e < E) ? ei[E + e] : (e - E);
    atomicAdd(&g_cnt[d], 1);
}

// --- 3-stage multi-block exclusive scan of g_cnt -> g_rowptr / g_cur -----
__global__ void k_scanA(int n) {
    int idx = blockIdx.x * SCHUNK + threadIdx.x;
    int v = (idx < n) ? g_cnt[idx] : 0;
    __shared__ int wsum[16];
    int lane = threadIdx.x & 31, wid = threadIdx.x >> 5;
    int s = v;
    #pragma unroll
    for (int off = 1; off < 32; off <<= 1) {
        int t = __shfl_up_sync(0xffffffffu, s, off);
        if (lane >= off) s += t;
    }
    if (lane == 31) wsum[wid] = s;
    __syncthreads();
    if (threadIdx.x == 0) {
        int tot = 0;
        #pragma unroll
        for (int w = 0; w < 16; w++) tot += wsum[w];
        g_bsum[blockIdx.x] = tot;
    }
}

__global__ void k_scanB(int nb, int n) {
    __shared__ int wsum[8];
    int lane = threadIdx.x & 31, wid = threadIdx.x >> 5;
    int v = (threadIdx.x < nb) ? g_bsum[threadIdx.x] : 0;
    int incl = v;
    #pragma unroll
    for (int off = 1; off < 32; off <<= 1) {
        int t = __shfl_up_sync(0xffffffffu, incl, off);
        if (lane >= off) incl += t;
    }
    if (lane == 31) wsum[wid] = incl;
    __syncthreads();
    if (wid == 0 && lane < 8) {
        int s = wsum[lane];
        #pragma unroll
        for (int off = 1; off < 8; off <<= 1) {
            int t = __shfl_up_sync(0xffu, s, off);
            if (lane >= off) s += t;
        }
        wsum[lane] = s;
    }
    __syncthreads();
    int woff = (wid == 0) ? 0 : wsum[wid - 1];
    int excl = woff + incl - v;
    if (threadIdx.x < nb) g_bsum[threadIdx.x] = excl;
    if (threadIdx.x == nb - 1) g_rowptr[n] = excl + v;
}

__global__ void k_scanC(int n) {
    int idx = blockIdx.x * SCHUNK + threadIdx.x;
    int v = (idx < n) ? g_cnt[idx] : 0;
    __shared__ int wsum[16];
    int lane = threadIdx.x & 31, wid = threadIdx.x >> 5;
    int incl = v;
    #pragma unroll
    for (int off = 1; off < 32; off <<= 1) {
        int t = __shfl_up_sync(0xffffffffu, incl, off);
        if (lane >= off) incl += t;
    }
    if (lane == 31) wsum[wid] = incl;
    __syncthreads();
    if (wid == 0 && lane < 16) {
        int s = wsum[lane];
        #pragma unroll
        for (int off = 1; off < 16; off <<= 1) {
            int t = __shfl_up_sync(0xffffu, s, off);
            if (lane >= off) s += t;
        }
        wsum[lane] = s;
    }
    __syncthreads();
    int woff = (wid == 0) ? 0 : wsum[wid - 1];
    int excl = g_bsum[blockIdx.x] + woff + incl - v;
    if (idx < n) { g_rowptr[idx] = excl; g_cur[idx] = excl; }
}

__global__ void k_scatter(const int* __restrict__ ei, int E, int etot) {
    int e = blockIdx.x * blockDim.x + threadIdx.x;
    if (e >= etot) return;
    int s, d;
    if (e < E) { s = ei[e]; d = ei[E + e]; }
    else       { s = d = e - E; }
    int pos = atomicAdd(&g_cur[d], 1);
    g_perm[pos] = e;
    g_csrc[pos] = s;
}

// ---- dual GEMM: g_xl = x@Wl + bl, g_xr = x@Wr + br  (64 output cols) ----
// 256 threads = 8 warps; warp handles 8 rows; lane handles 2 cols of each W.
template <int K>
__global__ void __launch_bounds__(256, 2)
k_gemm2(const float* __restrict__ xext, int from_gh,
        const float* __restrict__ Wl, const float* __restrict__ bl,
        const float* __restrict__ Wr, const float* __restrict__ br,
        int nrows) {
    extern __shared__ float sm[];
    float* sWl = sm;                 // K*64
    float* sWr = sm + K * 64;        // K*64
    float* sX  = sm + 2 * K * 64;    // 8 warps * 8 rows * K
    const float* x = from_gh ? g_h : xext;

    for (int i = threadIdx.x; i < K * 64; i += 256) { sWl[i] = Wl[i]; sWr[i] = Wr[i]; }
    __syncthreads();

    int warp = threadIdx.x >> 5, lane = threadIdx.x & 31;
    float2 bvl = ((const float2*)bl)[lane];
    float2 bvr = ((const float2*)br)[lane];
    float* sx = sX + warp * 8 * K;
    const int NV = K / 4;            // float4s per row

    for (int base = (blockIdx.x * 8 + warp) * 8; base < nrows; base += gridDim.x * 64) {
        #pragma unroll
        for (int r = 0; r < 8; r++) {
            int row = base + r;
            if (row < nrows && lane < NV)
                *(float4*)&sx[r * K + lane * 4] = *(const float4*)&x[(size_t)row * K + lane * 4];
        }
        __syncwarp();
        float2 accl[8], accr[8];
        #pragma unroll
        for (int r = 0; r < 8; r++) { accl[r] = make_float2(0.f, 0.f); accr[r] = make_float2(0.f, 0.f); }
        for (int k0 = 0; k0 < K; k0 += 4) {
            float4 xv[8];
            #pragma unroll
            for (int r = 0; r < 8; r++) xv[r] = *(const float4*)&sx[r * K + k0];
            #pragma unroll
            for (int kk = 0; kk < 4; kk++) {
                float2 wl = *(const float2*)&sWl[(k0 + kk) * 64 + 2 * lane];
                float2 wr = *(const float2*)&sWr[(k0 + kk) * 64 + 2 * lane];
                #pragma unroll
                for (int r = 0; r < 8; r++) {
                    float xs = ((const float*)&xv[r])[kk];
                    accl[r].x = fmaf(xs, wl.x, accl[r].x);
                    accl[r].y = fmaf(xs, wl.y, accl[r].y);
                    accr[r].x = fmaf(xs, wr.x, accr[r].x);
                    accr[r].y = fmaf(xs, wr.y, accr[r].y);
                }
            }
        }
        #pragma unroll
        for (int r = 0; r < 8; r++) {
            int row = base + r;
            if (row < nrows) {
                *(float2*)&g_xl[(size_t)row * 64 + 2 * lane] =
                    make_float2(accl[r].x + bvl.x, accl[r].y + bvl.y);
                *(float2*)&g_xr[(size_t)row * 64 + 2 * lane] =
                    make_float2(accr[r].x + bvr.x, accr[r].y + bvr.y);
            }
        }
        __syncwarp();
    }
}

// ---- fused per-node edge phase, 4x unrolled edge loop --------------------
// lane covers feature indices {2*lane, 2*lane+1}; head = lane>>3.
__global__ void k_node(int out_to_gh, float* __restrict__ outext,
                       const float* __restrict__ att, const float* __restrict__ bias,
                       float* __restrict__ alpha, int n) {
    int node = blockIdx.x * 8 + (threadIdx.x >> 5);
    if (node >= n) return;
    int lane = threadIdx.x & 31;
    int head = lane >> 3;
    float* outp = out_to_gh ? g_h : outext;

    int rs = g_rowptr[node], re = g_rowptr[node + 1];
    float2 xrv = *(const float2*)&g_xr[(size_t)node * 64 + 2 * lane];
    float2 av  = ((const float2*)att)[lane];

    float denom = 0.f;
    float2 acc = make_float2(0.f, 0.f);

    int pos = rs;
    for (; pos + 4 <= re; pos += 4) {
        int s0 = g_csrc[pos], s1 = g_csrc[pos + 1], s2 = g_csrc[pos + 2], s3 = g_csrc[pos + 3];
        float2 x0 = *(const float2*)&g_xl[(size_t)s0 * 64 + 2 * lane];
        float2 x1 = *(const float2*)&g_xl[(size_t)s1 * 64 + 2 * lane];
        float2 x2 = *(const float2*)&g_xl[(size_t)s2 * 64 + 2 * lane];
        float2 x3 = *(const float2*)&g_xl[(size_t)s3 * 64 + 2 * lane];
        float m0x = x0.x + xrv.x, m0y = x0.y + xrv.y;
        float m1x = x1.x + xrv.x, m1y = x1.y + xrv.y;
        float m2x = x2.x + xrv.x, m2y = x2.y + xrv.y;
        float m3x = x3.x + xrv.x, m3y = x3.y + xrv.y;
        m0x = m0x > 0.f ? m0x : NEGSLOPE * m0x;  m0y = m0y > 0.f ? m0y : NEGSLOPE * m0y;
        m1x = m1x > 0.f ? m1x : NEGSLOPE * m1x;  m1y = m1y > 0.f ? m1y : NEGSLOPE * m1y;
        m2x = m2x > 0.f ? m2x : NEGSLOPE * m2x;  m2y = m2y > 0.f ? m2y : NEGSLOPE * m2y;
        m3x = m3x > 0.f ? m3x : NEGSLOPE * m3x;  m3y = m3y > 0.f ? m3y : NEGSLOPE * m3y;
        float p0 = m0x * av.x + m0y * av.y;
        float p1 = m1x * av.x + m1y * av.y;
        float p2 = m2x * av.x + m2y * av.y;
        float p3 = m3x * av.x + m3y * av.y;
        p0 += __shfl_xor_sync(0xffffffffu, p0, 1);
        p1 += __shfl_xor_sync(0xffffffffu, p1, 1);
        p2 += __shfl_xor_sync(0xffffffffu, p2, 1);
        p3 += __shfl_xor_sync(0xffffffffu, p3, 1);
        p0 += __shfl_xor_sync(0xffffffffu, p0, 2);
        p1 += __shfl_xor_sync(0xffffffffu, p1, 2);
        p2 += __shfl_xor_sync(0xffffffffu, p2, 2);
        p3 += __shfl_xor_sync(0xffffffffu, p3, 2);
        p0 += __shfl_xor_sync(0xffffffffu, p0, 4);
        p1 += __shfl_xor_sync(0xffffffffu, p1, 4);
        p2 += __shfl_xor_sync(0xffffffffu, p2, 4);
        p3 += __shfl_xor_sync(0xffffffffu, p3, 4);
        float e0 = __expf(p0), e1 = __expf(p1), e2 = __expf(p2), e3 = __expf(p3);
        if ((lane & 7) == 0) {
            ((float*)&g_sc[pos    ])[head] = e0;
            ((float*)&g_sc[pos + 1])[head] = e1;
            ((float*)&g_sc[pos + 2])[head] = e2;
            ((float*)&g_sc[pos + 3])[head] = e3;
        }
        denom += (e0 + e1) + (e2 + e3);
        acc.x = fmaf(e0, x0.x, acc.x);  acc.y = fmaf(e0, x0.y, acc.y);
        acc.x = fmaf(e1, x1.x, acc.x);  acc.y = fmaf(e1, x1.y, acc.y);
        acc.x = fmaf(e2, x2.x, acc.x);  acc.y = fmaf(e2, x2.y, acc.y);
        acc.x = fmaf(e3, x3.x, acc.x);  acc.y = fmaf(e3, x3.y, acc.y);
    }
    for (; pos < re; pos++) {
        int s = g_csrc[pos];
        float2 xlv = *(const float2*)&g_xl[(size_t)s * 64 + 2 * lane];
        float mx = xlv.x + xrv.x;
        float my = xlv.y + xrv.y;
        mx = mx > 0.f ? mx : NEGSLOPE * mx;
        my = my > 0.f ? my : NEGSLOPE * my;
        float p = mx * av.x + my * av.y;
        p += __shfl_xor_sync(0xffffffffu, p, 1);
        p += __shfl_xor_sync(0xffffffffu, p, 2);
        p += __shfl_xor_sync(0xffffffffu, p, 4);
        float e = __expf(p);
        if ((lane & 7) == 0) ((float*)&g_sc[pos])[head] = e;
        denom += e;
        acc.x = fmaf(e, xlv.x, acc.x);
        acc.y = fmaf(e, xlv.y, acc.y);
    }
    float rcp = 1.f / (denom + EPSV);

    float2 bv = ((const float2*)bias)[lane];
    float ox = fmaxf(fmaf(acc.x, rcp, bv.x), 0.f);
    float oy = fmaxf(fmaf(acc.y, rcp, bv.y), 0.f);
    *(float2*)&outp[(size_t)node * 64 + 2 * lane] = make_float2(ox, oy);

    // alpha writeback: lane-parallel over CSR positions, float4 per edge
    float r0 = __shfl_sync(0xffffffffu, rcp, 0);
    float r1 = __shfl_sync(0xffffffffu, rcp, 8);
    float r2 = __shfl_sync(0xffffffffu, rcp, 16);
    float r3 = __shfl_sync(0xffffffffu, rcp, 24);
    __syncwarp();
    for (int q = rs + lane; q < re; q += 32) {
        float4 e4 = g_sc[q];
        float4 a4 = make_float4(e4.x * r0, e4.y * r1, e4.z * r2, e4.w * r3);
        *(float4*)&alpha[(size_t)g_perm[q] * 4] = a4;
    }
}

// ---------------- launch ----------------
extern "C" void kernel_launch(void* const* d_in, const int* in_sizes, int n_in,
                              void* d_out, int out_size) {
    const float* x     = (const float*)d_in[0];
    const int*   ei    = (const int*)d_in[1];      // int32 edge index
    const float* Wl1   = (const float*)d_in[2];
    const float* bl1   = (const float*)d_in[3];
    const float* Wr1   = (const float*)d_in[4];
    const float* br1   = (const float*)d_in[5];
    const float* att1  = (const float*)d_in[6];
    const float* bias1 = (const float*)d_in[7];
    const float* Wl2   = (const float*)d_in[8];
    const float* bl2   = (const float*)d_in[9];
    const float* Wr2   = (const float*)d_in[10];
    const float* br2   = (const float*)d_in[11];
    const float* att2  = (const float*)d_in[12];
    const float* bias2 = (const float*)d_in[13];

    int n    = in_sizes[0] / 128;  // 100000
    int E    = in_sizes[1] / 2;    // 1600000
    int etot = E + n;              // 1700000
    int nb   = (n + SCHUNK - 1) / SCHUNK;

    float* out    = (float*)d_out;
    float* outh   = out;
    float* alpha1 = out + (size_t)n * 64;
    float* alpha2 = alpha1 + (size_t)etot * 4;

    // dynamic smem opt-in (K=128: 96KB; K=64: 48KB)
    cudaFuncSetAttribute(k_gemm2<128>, cudaFuncAttributeMaxDynamicSharedMemorySize, 98304);
    cudaFuncSetAttribute(k_gemm2<64>,  cudaFuncAttributeMaxDynamicSharedMemorySize, 49152);

    // CSR build (shared by both layers)
    k_zero<<<(n + 511) / 512, 512>>>(n);
    k_count<<<(etot + 511) / 512, 512>>>(ei, E, etot);
    k_scanA<<<nb, SCHUNK>>>(n);
    k_scanB<<<1, 256>>>(nb, n);
    k_scanC<<<nb, SCHUNK>>>(n);
    k_scatter<<<(etot + 511) / 512, 512>>>(ei, E, etot);

    // layer 1
    k_gemm2<128><<<296, 256, 98304>>>(x, 0, Wl1, bl1, Wr1, br1, n);
    k_node<<<(n + 7) / 8, 256>>>(/*out_to_gh=*/1, nullptr, att1, bias1, alpha1, n);

    // layer 2 (input = g_h)
    k_gemm2<64><<<296, 256, 49152>>>(nullptr, 1, Wl2, bl2, Wr2, br2, n);
    k_node<<<(n + 7) / 8, 256>>>(/*out_to_gh=*/0, outh, att2, bias2, alpha2, n);
}